// round 9
// baseline (speedup 1.0000x reference)
#include <cuda_runtime.h>
#include <cuda_fp16.h>
#include <cstdint>

#define BATCH 8192
#define IND   1024
#define OUTD  1024
#define DD    8
#define TM    64
#define TN    128
#define KC    64
#define NSTEPS 128
#define NTHREADS 128

// SMEM: 6-tile B ring (2 group-buffers x 3 tiles x 16KB) + bias + w table
#define SM_B     0
#define SM_BIAS  98304
#define SM_W     102400
#define SM_ALLOC 103424

__device__ __half g_wh[(size_t)DD * OUTD * IND];

static __device__ __forceinline__ uint32_t smem_u32(const void* p) {
    uint32_t a;
    asm("{ .reg .u64 t; cvta.to.shared.u64 t, %1; cvt.u32.u64 %0, t; }" : "=r"(a) : "l"(p));
    return a;
}
static __device__ __forceinline__ void cp16(uint32_t dst, const void* src) {
    asm volatile("cp.async.cg.shared.global [%0], [%1], 16;" :: "r"(dst), "l"(src));
}
static __device__ __forceinline__ void cp_commit() {
    asm volatile("cp.async.commit_group;" ::: "memory");
}
static __device__ __forceinline__ void cp_wait2() {
    asm volatile("cp.async.wait_group 2;" ::: "memory");
}
static __device__ __forceinline__ void cp_wait0() {
    asm volatile("cp.async.wait_group 0;" ::: "memory");
}
static __device__ __forceinline__ void ldsm4(uint32_t* r, uint32_t addr) {
    asm volatile("ldmatrix.sync.aligned.m8n8.x4.shared.b16 {%0,%1,%2,%3}, [%4];"
                 : "=r"(r[0]), "=r"(r[1]), "=r"(r[2]), "=r"(r[3]) : "r"(addr));
}
static __device__ __forceinline__ void mma16816(float* c, uint32_t a0, uint32_t a1,
                                                uint32_t a2, uint32_t a3,
                                                uint32_t b0, uint32_t b1) {
    asm volatile("mma.sync.aligned.m16n8k16.row.col.f32.f16.f16.f32 "
                 "{%0,%1,%2,%3}, {%4,%5,%6,%7}, {%8,%9}, {%0,%1,%2,%3};"
                 : "+f"(c[0]), "+f"(c[1]), "+f"(c[2]), "+f"(c[3])
                 : "r"(a0), "r"(a1), "r"(a2), "r"(a3), "r"(b0), "r"(b1));
}
static __device__ __forceinline__ uint32_t packh2(float x, float y) {
    __half2 h = __floats2half2_rn(x, y);
    return *reinterpret_cast<uint32_t*>(&h);
}
static __device__ __forceinline__ uint32_t hmul2u(uint32_t a, uint32_t b) {
    __half2 r = __hmul2(*reinterpret_cast<__half2*>(&a), *reinterpret_cast<__half2*>(&b));
    return *reinterpret_cast<uint32_t*>(&r);
}
// load half w[row,d] from SMEM table, broadcast to half2
static __device__ __forceinline__ uint32_t ld_whd(uint32_t addr) {
    uint16_t hv;
    asm("ld.shared.u16 %0, [%1];" : "=h"(hv) : "r"(addr));
    uint32_t t = hv, r;
    asm("prmt.b32 %0, %1, %1, 0x1010;" : "=r"(r) : "r"(t));
    return r;
}

// stage one 128n x 64k fp16 tile (swizzled 128B rows): 8 cp16/thread
static __device__ __forceinline__ void copy_b_tile(uint32_t dstbase, int tid,
                                                   const __half* wp) {
    #pragma unroll
    for (int j = 0; j < 8; j++) {
        int g = tid + j * NTHREADS;
        int n = g >> 3, c = g & 7;
        uint32_t off = (uint32_t)(n * 128 + c * 16);
        off ^= (uint32_t)((n & 7) << 4);
        cp16(dstbase + off, wp + (size_t)n * IND + c * 8);
    }
}

__global__ void dynlin_wconv_kernel(const float* __restrict__ w) {
    size_t i = ((size_t)blockIdx.x * blockDim.x + threadIdx.x) * 4;
    float4 v = *reinterpret_cast<const float4*>(w + i);
    *reinterpret_cast<__half2*>(g_wh + i)     = __floats2half2_rn(v.x, v.y);
    *reinterpret_cast<__half2*>(g_wh + i + 2) = __floats2half2_rn(v.z, v.w);
}

__global__ void __launch_bounds__(NTHREADS, 2)
dynlin_main_kernel(const float* __restrict__ input,
                   const float* __restrict__ wv,
                   const float* __restrict__ biases,
                   float* __restrict__ out)
{
    extern __shared__ char sm[];
    const uint32_t sb = smem_u32(sm);
    const int tid  = threadIdx.x;
    const int lane = tid & 31;
    const int wid  = tid >> 5;
    const int wm   = wid & 1;          // 2 warp rows x 32
    const int wn   = wid >> 1;         // 2 warp cols x 64
    const int col0 = blockIdx.x * TN;
    const int row0 = blockIdx.y * TM;

    {   // bias tile [8][128]
        int d = tid >> 4, c = (tid & 15) * 8;
        float4 b0 = *reinterpret_cast<const float4*>(biases + (size_t)d * OUTD + col0 + c);
        float4 b1 = *reinterpret_cast<const float4*>(biases + (size_t)d * OUTD + col0 + c + 4);
        *reinterpret_cast<float4*>(sm + SM_BIAS + (d * TN + c) * 4)     = b0;
        *reinterpret_cast<float4*>(sm + SM_BIAS + (d * TN + c + 4) * 4) = b1;
    }
    if (tid < 64) {      // w table: half w[64 rows][8 d]
        const float* wp = wv + (size_t)(row0 + tid) * DD;
        float4 w0 = *reinterpret_cast<const float4*>(wp);
        float4 w1 = *reinterpret_cast<const float4*>(wp + 4);
        __half2 h0 = __floats2half2_rn(w0.x, w0.y);
        __half2 h1 = __floats2half2_rn(w0.z, w0.w);
        __half2 h2 = __floats2half2_rn(w1.x, w1.y);
        __half2 h3 = __floats2half2_rn(w1.z, w1.w);
        uint4 pk;
        pk.x = *reinterpret_cast<uint32_t*>(&h0);
        pk.y = *reinterpret_cast<uint32_t*>(&h1);
        pk.z = *reinterpret_cast<uint32_t*>(&h2);
        pk.w = *reinterpret_cast<uint32_t*>(&h3);
        *reinterpret_cast<uint4*>(sm + SM_W + tid * 16) = pk;
    }

    float acc[2][8][4];
    #pragma unroll
    for (int mt = 0; mt < 2; mt++)
        #pragma unroll
        for (int nt = 0; nt < 8; nt++)
            #pragma unroll
            for (int k = 0; k < 4; k++) acc[mt][nt][k] = 0.f;

    // prologue: tiles 0,1,2 into group-buffer 0, one commit group each
    #pragma unroll
    for (int t = 0; t < 3; t++) {
        const int d = t & 7, ic = t >> 3;
        copy_b_tile(sb + SM_B + (uint32_t)t * 16384, tid,
                    g_wh + ((size_t)d * OUTD + col0) * IND + ic * KC);
        cp_commit();
    }

    // per-step whd SMEM base addresses for this thread's 4 acc rows
    uint32_t waddr[2][2];
    #pragma unroll
    for (int mt = 0; mt < 2; mt++)
        #pragma unroll
        for (int rs = 0; rs < 2; rs++)
            waddr[mt][rs] = sb + SM_W +
                (uint32_t)((wm * 32 + mt * 16 + rs * 8 + (lane >> 2)) * 8) * 2;

    uint32_t inch[2][4][2][2];   // input as half2, refreshed every 8 steps

    #pragma unroll 1
    for (int g = 0; g < 43; g++) {
        __syncthreads();         // group boundary: prior-group reads complete
        #pragma unroll
        for (int st = 0; st < 3; st++) {
            const int s = g * 3 + st;
            if (s >= NSTEPS) break;

            if ((s & 7) == 0) {  // refresh input cache for ic = s>>3
                const int i0 = (s >> 3) * KC;
                #pragma unroll
                for (int mt = 0; mt < 2; mt++)
                    #pragma unroll
                    for (int rs = 0; rs < 2; rs++) {
                        int r = row0 + wm * 32 + mt * 16 + rs * 8 + (lane >> 2);
                        const float* ip = input + (size_t)r * IND + i0 + (lane & 3) * 2;
                        #pragma unroll
                        for (int kb = 0; kb < 4; kb++)
                            #pragma unroll
                            for (int hs = 0; hs < 2; hs++) {
                                float2 v = *reinterpret_cast<const float2*>(
                                    ip + kb * 16 + hs * 8);
                                inch[mt][kb][rs][hs] = packh2(v.x, v.y);
                            }
                    }
            }

            cp_wait2();          // tile s resident (<=2 younger pending)

            {   // staggered fetch: tile s+3 (clamped; dummy past end is harmless)
                const int t  = (s + 3) & 127;
                const int d  = t & 7, ic = t >> 3;
                const uint32_t dst = sb + SM_B +
                    (uint32_t)(((s + 3) / 3) & 1) * 49152 + (uint32_t)st * 16384;
                copy_b_tile(dst, tid, g_wh + ((size_t)d * OUTD + col0) * IND + ic * KC);
                cp_commit();
            }

            const int d = s & 7;
            uint32_t whd[2][2];
            #pragma unroll
            for (int mt = 0; mt < 2; mt++)
                #pragma unroll
                for (int rs = 0; rs < 2; rs++)
                    whd[mt][rs] = ld_whd(waddr[mt][rs] + (uint32_t)d * 2);

            const uint32_t bbase = sb + SM_B + (uint32_t)(g & 1) * 49152
                                 + (uint32_t)st * 16384;
            #pragma unroll
            for (int kb = 0; kb < 4; kb++) {
                uint32_t bf[16];
                #pragma unroll
                for (int pr = 0; pr < 4; pr++) {
                    int n = wn * 64 + pr * 16 + (lane & 7) + ((lane >> 4) << 3);
                    uint32_t off = (uint32_t)(n * 128 + kb * 32 + ((lane >> 3) & 1) * 16);
                    off ^= (uint32_t)((n & 7) << 4);
                    ldsm4(bf + pr * 4, bbase + off);
                }
                #pragma unroll
                for (int mt = 0; mt < 2; mt++) {
                    uint32_t a0 = hmul2u(inch[mt][kb][0][0], whd[mt][0]);
                    uint32_t a1 = hmul2u(inch[mt][kb][1][0], whd[mt][1]);
                    uint32_t a2 = hmul2u(inch[mt][kb][0][1], whd[mt][0]);
                    uint32_t a3 = hmul2u(inch[mt][kb][1][1], whd[mt][1]);
                    #pragma unroll
                    for (int nt = 0; nt < 8; nt++) {
                        int bi = (nt >> 1) * 4 + (nt & 1) * 2;
                        mma16816(acc[mt][nt], a0, a1, a2, a3, bf[bi], bf[bi + 1]);
                    }
                }
            }
        }
    }

    cp_wait0();                  // drain dummy fetches before exit

    // epilogue: out = acc + sum_d w[row,d]*biases[d,col]  (fp32 w reloaded)
    float wr[2][2][8];
    #pragma unroll
    for (int mt = 0; mt < 2; mt++)
        #pragma unroll
        for (int rs = 0; rs < 2; rs++) {
            int r = row0 + wm * 32 + mt * 16 + rs * 8 + (lane >> 2);
            float4 w0 = *reinterpret_cast<const float4*>(wv + (size_t)r * DD);
            float4 w1 = *reinterpret_cast<const float4*>(wv + (size_t)r * DD + 4);
            wr[mt][rs][0]=w0.x; wr[mt][rs][1]=w0.y; wr[mt][rs][2]=w0.z; wr[mt][rs][3]=w0.w;
            wr[mt][rs][4]=w1.x; wr[mt][rs][5]=w1.y; wr[mt][rs][6]=w1.z; wr[mt][rs][7]=w1.w;
        }
    #pragma unroll
    for (int nt = 0; nt < 8; nt++) {
        int coff = wn * 64 + nt * 8 + (lane & 3) * 2;
        float2 bv[8];
        #pragma unroll
        for (int d = 0; d < DD; d++)
            bv[d] = *reinterpret_cast<const float2*>(sm + SM_BIAS + (d * TN + coff) * 4);
        #pragma unroll
        for (int mt = 0; mt < 2; mt++)
            #pragma unroll
            for (int rs = 0; rs < 2; rs++) {
                float s0 = 0.f, s1 = 0.f;
                #pragma unroll
                for (int d = 0; d < DD; d++) {
                    s0 = fmaf(wr[mt][rs][d], bv[d].x, s0);
                    s1 = fmaf(wr[mt][rs][d], bv[d].y, s1);
                }
                int r = row0 + wm * 32 + mt * 16 + rs * 8 + (lane >> 2);
                float2 o;
                o.x = acc[mt][nt][rs * 2 + 0] + s0;
                o.y = acc[mt][nt][rs * 2 + 1] + s1;
                *reinterpret_cast<float2*>(out + (size_t)r * OUTD + col0 + coff) = o;
            }
    }
}

extern "C" void kernel_launch(void* const* d_in, const int* in_sizes, int n_in,
                              void* d_out, int out_size) {
    const float* input = nullptr;
    const float* wv = nullptr;
    const float* weights = nullptr;
    const float* biases = nullptr;
    for (int i = 0; i < n_in; i++) {
        long long sz = in_sizes[i];
        if (sz == (long long)BATCH * DD)           wv = (const float*)d_in[i];
        else if (sz == (long long)DD * OUTD)       biases = (const float*)d_in[i];
        else if (sz == (long long)BATCH * IND) {
            if (!input) input = (const float*)d_in[i];
            else        weights = (const float*)d_in[i];
        }
    }
    float* out = (float*)d_out;

    dynlin_wconv_kernel<<<(DD * OUTD * IND) / (256 * 4), 256>>>(weights);

    cudaFuncSetAttribute(dynlin_main_kernel,
                         cudaFuncAttributeMaxDynamicSharedMemorySize, SM_ALLOC);
    dim3 grid(OUTD / TN, BATCH / TM);
    dynlin_main_kernel<<<grid, NTHREADS, SM_ALLOC>>>(input, wv, biases, out);
}

// round 10
// speedup vs baseline: 1.1804x; 1.1804x over previous
#include <cuda_runtime.h>
#include <cuda_fp16.h>
#include <cstdint>

#define BATCH 8192
#define IND   1024
#define OUTD  1024
#define DD    8
#define TM    64
#define TN    128
#define KC    64
#define NIC   16
#define NPAIRS 64
#define NTHREADS 128

// SMEM: 2 pair-buffers (each 2x16KB tiles) + bias + mbarriers
#define SM_B     0
#define SM_BIAS  65536
#define SM_MBAR  69632          // full[0],full[1],empty[0],empty[1] (8B each)
#define SM_ALLOC 69696

__device__ __half g_wh[(size_t)DD * OUTD * IND];

static __device__ __forceinline__ uint32_t smem_u32(const void* p) {
    uint32_t a;
    asm("{ .reg .u64 t; cvta.to.shared.u64 t, %1; cvt.u32.u64 %0, t; }" : "=r"(a) : "l"(p));
    return a;
}
static __device__ __forceinline__ void cp16(uint32_t dst, const void* src) {
    asm volatile("cp.async.cg.shared.global [%0], [%1], 16;" :: "r"(dst), "l"(src));
}
static __device__ __forceinline__ void cp_mbar_arrive(uint32_t mbar) {
    asm volatile("cp.async.mbarrier.arrive.noinc.shared.b64 [%0];" :: "r"(mbar) : "memory");
}
static __device__ __forceinline__ void mbar_arrive(uint32_t mbar) {
    asm volatile("mbarrier.arrive.shared.b64 _, [%0];" :: "r"(mbar) : "memory");
}
static __device__ __forceinline__ void mbar_wait(uint32_t mbar, uint32_t parity) {
    asm volatile(
        "{\n\t.reg .pred P;\n\t"
        "L_%=:\n\t"
        "mbarrier.try_wait.parity.acquire.cta.shared::cta.b64 P, [%0], %1, 0x989680;\n\t"
        "@P bra.uni D_%=;\n\t"
        "bra.uni L_%=;\n\t"
        "D_%=:\n\t}"
        :: "r"(mbar), "r"(parity) : "memory");
}
static __device__ __forceinline__ void ldsm4(uint32_t* r, uint32_t addr) {
    asm volatile("ldmatrix.sync.aligned.m8n8.x4.shared.b16 {%0,%1,%2,%3}, [%4];"
                 : "=r"(r[0]), "=r"(r[1]), "=r"(r[2]), "=r"(r[3]) : "r"(addr));
}
static __device__ __forceinline__ void mma16816(float* c, uint32_t a0, uint32_t a1,
                                                uint32_t a2, uint32_t a3,
                                                uint32_t b0, uint32_t b1) {
    asm volatile("mma.sync.aligned.m16n8k16.row.col.f32.f16.f16.f32 "
                 "{%0,%1,%2,%3}, {%4,%5,%6,%7}, {%8,%9}, {%0,%1,%2,%3};"
                 : "+f"(c[0]), "+f"(c[1]), "+f"(c[2]), "+f"(c[3])
                 : "r"(a0), "r"(a1), "r"(a2), "r"(a3), "r"(b0), "r"(b1));
}
static __device__ __forceinline__ uint32_t packh2(float x, float y) {
    __half2 h = __floats2half2_rn(x, y);
    return *reinterpret_cast<uint32_t*>(&h);
}
static __device__ __forceinline__ uint32_t hmul2u(uint32_t a, uint32_t b) {
    __half2 r = __hmul2(*reinterpret_cast<__half2*>(&a), *reinterpret_cast<__half2*>(&b));
    return *reinterpret_cast<uint32_t*>(&r);
}

// stage one 128n x 64k fp16 tile (swizzled 128B rows): 8 cp16/thread
static __device__ __forceinline__ void copy_b_tile(uint32_t dstbase, int tid,
                                                   const __half* wp) {
    #pragma unroll
    for (int j = 0; j < 8; j++) {
        int g = tid + j * NTHREADS;
        int n = g >> 3, c = g & 7;
        uint32_t off = (uint32_t)(n * 128 + c * 16);
        off ^= (uint32_t)((n & 7) << 4);
        cp16(dstbase + off, wp + (size_t)n * IND + c * 8);
    }
}

__global__ void dynlin_wconv_kernel(const float* __restrict__ w) {
    size_t i = ((size_t)blockIdx.x * blockDim.x + threadIdx.x) * 4;
    float4 v = *reinterpret_cast<const float4*>(w + i);
    *reinterpret_cast<__half2*>(g_wh + i)     = __floats2half2_rn(v.x, v.y);
    *reinterpret_cast<__half2*>(g_wh + i + 2) = __floats2half2_rn(v.z, v.w);
}

__global__ void __launch_bounds__(NTHREADS, 2)
dynlin_main_kernel(const float* __restrict__ input,
                   const float* __restrict__ wv,
                   const float* __restrict__ biases,
                   float* __restrict__ out)
{
    extern __shared__ char sm[];
    const uint32_t sb = smem_u32(sm);
    const int tid  = threadIdx.x;
    const int lane = tid & 31;
    const int wid  = tid >> 5;
    const int wm   = wid & 1;          // 2 warp rows x 32
    const int wn   = wid >> 1;         // 2 warp cols x 64
    const int col0 = blockIdx.x * TN;
    const int row0 = blockIdx.y * TM;

    const uint32_t mb_full  = sb + SM_MBAR;       // full[0], full[1]
    const uint32_t mb_empty = sb + SM_MBAR + 16;  // empty[0], empty[1]

    if (tid == 0) {
        asm volatile("mbarrier.init.shared.b64 [%0], %1;" :: "r"(mb_full),      "r"(NTHREADS) : "memory");
        asm volatile("mbarrier.init.shared.b64 [%0], %1;" :: "r"(mb_full + 8),  "r"(NTHREADS) : "memory");
        asm volatile("mbarrier.init.shared.b64 [%0], %1;" :: "r"(mb_empty),     "r"(NTHREADS) : "memory");
        asm volatile("mbarrier.init.shared.b64 [%0], %1;" :: "r"(mb_empty + 8), "r"(NTHREADS) : "memory");
    }

    {   // bias tile [8][128]
        int d = tid >> 4, c = (tid & 15) * 8;
        float4 b0 = *reinterpret_cast<const float4*>(biases + (size_t)d * OUTD + col0 + c);
        float4 b1 = *reinterpret_cast<const float4*>(biases + (size_t)d * OUTD + col0 + c + 4);
        *reinterpret_cast<float4*>(sm + SM_BIAS + (d * TN + c) * 4)     = b0;
        *reinterpret_cast<float4*>(sm + SM_BIAS + (d * TN + c + 4) * 4) = b1;
    }

    float wr[2][2][8];
    #pragma unroll
    for (int mt = 0; mt < 2; mt++)
        #pragma unroll
        for (int rs = 0; rs < 2; rs++) {
            int r = row0 + wm * 32 + mt * 16 + rs * 8 + (lane >> 2);
            float4 w0 = *reinterpret_cast<const float4*>(wv + (size_t)r * DD);
            float4 w1 = *reinterpret_cast<const float4*>(wv + (size_t)r * DD + 4);
            wr[mt][rs][0]=w0.x; wr[mt][rs][1]=w0.y; wr[mt][rs][2]=w0.z; wr[mt][rs][3]=w0.w;
            wr[mt][rs][4]=w1.x; wr[mt][rs][5]=w1.y; wr[mt][rs][6]=w1.z; wr[mt][rs][7]=w1.w;
        }

    float acc[2][8][4];
    #pragma unroll
    for (int mt = 0; mt < 2; mt++)
        #pragma unroll
        for (int nt = 0; nt < 8; nt++)
            #pragma unroll
            for (int k = 0; k < 4; k++) acc[mt][nt][k] = 0.f;

    __syncthreads();   // mbarrier init visible before any arrive/wait

    // prologue: pair 0 into buffer 0, arrive on full[0] when copies land
    copy_b_tile(sb + SM_B, tid, g_wh + (size_t)col0 * IND);
    copy_b_tile(sb + SM_B + 16384, tid, g_wh + ((size_t)OUTD + col0) * IND);
    cp_mbar_arrive(mb_full);

    uint32_t inch[2][4][2][2];   // input as half2, refreshed per ic

    for (int ic = 0; ic < NIC; ic++) {
        const int i0 = ic * KC;
        #pragma unroll
        for (int mt = 0; mt < 2; mt++)
            #pragma unroll
            for (int rs = 0; rs < 2; rs++) {
                int r = row0 + wm * 32 + mt * 16 + rs * 8 + (lane >> 2);
                const float* ip = input + (size_t)r * IND + i0 + (lane & 3) * 2;
                #pragma unroll
                for (int kb = 0; kb < 4; kb++)
                    #pragma unroll
                    for (int hs = 0; hs < 2; hs++) {
                        float2 v = *reinterpret_cast<const float2*>(ip + kb * 16 + hs * 8);
                        inch[mt][kb][rs][hs] = packh2(v.x, v.y);
                    }
            }

        #pragma unroll
        for (int jp = 0; jp < 4; jp++) {
            const int j  = ic * 4 + jp;        // pair index
            const int pb = jp & 1;             // pair buffer (j&1 == jp&1)
            // compile-time parities: j = 4*ic + jp, 2*ic even
            const uint32_t pf = (uint32_t)((jp >> 1) & 1);            // full[pb]
            const uint32_t pe = (uint32_t)((jp == 0 || jp == 3) ? 1 : 0); // empty[pb^1] for pair j-1

            // hoist whd (register-only) above all waits
            uint32_t whd[2][2][2];
            #pragma unroll
            for (int half = 0; half < 2; half++)
                #pragma unroll
                for (int mt = 0; mt < 2; mt++)
                    #pragma unroll
                    for (int rs = 0; rs < 2; rs++) {
                        __half2 h = __half2half2(__float2half_rn(wr[mt][rs][jp * 2 + half]));
                        whd[half][mt][rs] = *reinterpret_cast<uint32_t*>(&h);
                    }

            // producer: fetch pair j+1 into buffer pb^1
            if (j + 1 < NPAIRS) {
                if (j >= 1) mbar_wait(mb_empty + (uint32_t)(pb ^ 1) * 8, pe);
                const int sn = 2 * (j + 1);
                const int nd = sn & 7, nic = sn >> 3;
                const __half* wp0 = g_wh + ((size_t)nd * OUTD + col0) * IND + nic * KC;
                const uint32_t nb = sb + SM_B + (uint32_t)(pb ^ 1) * 32768;
                copy_b_tile(nb, tid, wp0);
                copy_b_tile(nb + 16384, tid, wp0 + (size_t)OUTD * IND);
                cp_mbar_arrive(mb_full + (uint32_t)(pb ^ 1) * 8);
            }

            // consumer: wait pair j data
            mbar_wait(mb_full + (uint32_t)pb * 8, pf);

            #pragma unroll
            for (int half = 0; half < 2; half++) {
                const uint32_t bbase = sb + SM_B + (uint32_t)pb * 32768
                                     + (uint32_t)half * 16384;
                #pragma unroll
                for (int kb = 0; kb < 4; kb++) {
                    uint32_t bf[16];
                    #pragma unroll
                    for (int pr = 0; pr < 4; pr++) {
                        int n = wn * 64 + pr * 16 + (lane & 7) + ((lane >> 4) << 3);
                        uint32_t off = (uint32_t)(n * 128 + kb * 32 + ((lane >> 3) & 1) * 16);
                        off ^= (uint32_t)((n & 7) << 4);
                        ldsm4(bf + pr * 4, bbase + off);
                    }
                    #pragma unroll
                    for (int mt = 0; mt < 2; mt++) {
                        uint32_t a0 = hmul2u(inch[mt][kb][0][0], whd[half][mt][0]);
                        uint32_t a1 = hmul2u(inch[mt][kb][1][0], whd[half][mt][1]);
                        uint32_t a2 = hmul2u(inch[mt][kb][0][1], whd[half][mt][0]);
                        uint32_t a3 = hmul2u(inch[mt][kb][1][1], whd[half][mt][1]);
                        #pragma unroll
                        for (int nt = 0; nt < 8; nt++) {
                            int bi = (nt >> 1) * 4 + (nt & 1) * 2;
                            mma16816(acc[mt][nt], a0, a1, a2, a3, bf[bi], bf[bi + 1]);
                        }
                    }
                }
            }

            // reads of pair j done
            mbar_arrive(mb_empty + (uint32_t)pb * 8);
        }
    }

    __syncthreads();   // bias SMEM visibility for epilogue (cross-thread pattern)

    // epilogue: out = acc + sum_d w[row,d]*biases[d,col]
    #pragma unroll
    for (int nt = 0; nt < 8; nt++) {
        int coff = wn * 64 + nt * 8 + (lane & 3) * 2;
        float2 bv[8];
        #pragma unroll
        for (int d = 0; d < DD; d++)
            bv[d] = *reinterpret_cast<const float2*>(sm + SM_BIAS + (d * TN + coff) * 4);
        #pragma unroll
        for (int mt = 0; mt < 2; mt++)
            #pragma unroll
            for (int rs = 0; rs < 2; rs++) {
                float s0 = 0.f, s1 = 0.f;
                #pragma unroll
                for (int d = 0; d < DD; d++) {
                    s0 = fmaf(wr[mt][rs][d], bv[d].x, s0);
                    s1 = fmaf(wr[mt][rs][d], bv[d].y, s1);
                }
                int r = row0 + wm * 32 + mt * 16 + rs * 8 + (lane >> 2);
                float2 o;
                o.x = acc[mt][nt][rs * 2 + 0] + s0;
                o.y = acc[mt][nt][rs * 2 + 1] + s1;
                *reinterpret_cast<float2*>(out + (size_t)r * OUTD + col0 + coff) = o;
            }
    }
}

extern "C" void kernel_launch(void* const* d_in, const int* in_sizes, int n_in,
                              void* d_out, int out_size) {
    const float* input = nullptr;
    const float* wv = nullptr;
    const float* weights = nullptr;
    const float* biases = nullptr;
    for (int i = 0; i < n_in; i++) {
        long long sz = in_sizes[i];
        if (sz == (long long)BATCH * DD)           wv = (const float*)d_in[i];
        else if (sz == (long long)DD * OUTD)       biases = (const float*)d_in[i];
        else if (sz == (long long)BATCH * IND) {
            if (!input) input = (const float*)d_in[i];
            else        weights = (const float*)d_in[i];
        }
    }
    float* out = (float*)d_out;

    dynlin_wconv_kernel<<<(DD * OUTD * IND) / (256 * 4), 256>>>(weights);

    cudaFuncSetAttribute(dynlin_main_kernel,
                         cudaFuncAttributeMaxDynamicSharedMemorySize, SM_ALLOC);
    dim3 grid(OUTD / TN, BATCH / TM);
    dynlin_main_kernel<<<grid, NTHREADS, SM_ALLOC>>>(input, wv, biases, out);
}